// round 16
// baseline (speedup 1.0000x reference)
#include <cuda_runtime.h>
#include <cstdint>

#define H 256
#define B 32
#define S 1024
#define NL 4
#define NE (H * B)              // 8192
#define G4 (4 * H)              // 1024
#define MROWS (S * B)           // 32768
#define LSTRIDE ((S + 1) * NE)  // per-layer h0/c0 slab stride

// -------- static scratch (allowed: __device__ globals) --------
__device__ float g_gates[(size_t)MROWS * G4];   // 128 MB: [t*B+b][4H]
__device__ float g_xbuf0[(size_t)MROWS * H];    // 32 MB:  [t*B+b][H]
__device__ float g_xbuf1[(size_t)MROWS * H];    // 32 MB

// -------- helpers --------
__device__ __forceinline__ void ffma2(unsigned long long& d,
                                      unsigned long long a,
                                      unsigned long long b) {
    asm("fma.rn.f32x2 %0, %1, %2, %0;" : "+l"(d) : "l"(a), "l"(b));
}
__device__ __forceinline__ unsigned long long dup2(float a) {
    unsigned long long r;
    asm("mov.b64 %0, {%1, %1};" : "=l"(r) : "f"(a));
    return r;
}
__device__ __forceinline__ float2 unpack2(unsigned long long v) {
    float2 f;
    asm("mov.b64 {%0, %1}, %2;" : "=f"(f.x), "=f"(f.y) : "l"(v));
    return f;
}
__device__ __forceinline__ uint32_t smem_u32(const void* p) {
    return (uint32_t)__cvta_generic_to_shared(p);
}
__device__ __forceinline__ uint32_t ctarank() {
    uint32_t r;
    asm("mov.u32 %0, %%cluster_ctarank;" : "=r"(r));
    return r;
}
__device__ __forceinline__ uint32_t mapa_rank(uint32_t laddr, int r) {
    uint32_t ra;
    asm("mapa.shared::cluster.u32 %0, %1, %2;" : "=r"(ra) : "r"(laddr), "r"(r));
    return ra;
}
// fast, branch-free activations (rel err ~1e-6; saturate correctly)
__device__ __forceinline__ float fsigm(float x) {
    return __fdividef(1.0f, 1.0f + __expf(-x));
}
__device__ __forceinline__ float ftanh(float x) {
    return __fdividef(2.0f, 1.0f + __expf(-2.0f * x)) - 1.0f;
}
__device__ __forceinline__ void mbar_init(uint32_t a, int cnt) {
    asm volatile("mbarrier.init.shared.b64 [%0], %1;" :: "r"(a), "r"(cnt) : "memory");
}
__device__ __forceinline__ void mbar_expect(uint32_t a, uint32_t bytes) {
    asm volatile("mbarrier.arrive.expect_tx.shared.b64 _, [%0], %1;"
                 :: "r"(a), "r"(bytes) : "memory");
}
__device__ __forceinline__ void st_async_b64(uint32_t dst, unsigned long long v,
                                             uint32_t rbar) {
    asm volatile(
        "st.async.weak.shared::cluster.mbarrier::complete_tx::bytes.b64 [%0], %1, [%2];"
        :: "r"(dst), "l"(v), "r"(rbar) : "memory");
}
__device__ __forceinline__ void mbar_wait(uint32_t a, uint32_t parity) {
    uint32_t done;
    asm volatile(
        "{\n\t.reg .pred p;\n\t"
        "mbarrier.try_wait.parity.acquire.cta.shared::cta.b64 p, [%1], %2;\n\t"
        "selp.b32 %0, 1, 0, p;\n\t}"
        : "=r"(done) : "r"(a), "r"(parity) : "memory");
    if (!done) {
        asm volatile(
            "{\n\t.reg .pred P1;\n\t"
            "W_%=:\n\t"
            "mbarrier.try_wait.parity.acquire.cta.shared::cta.b64 P1, [%0], %1, 0x989680;\n\t"
            "@P1 bra.uni D_%=;\n\t"
            "bra.uni W_%=;\n\t"
            "D_%=:\n\t}"
            :: "r"(a), "r"(parity) : "memory");
    }
}

// ============================================================
// GEMM: C[M=32768, N=1024] = A[M,256] @ W^T + bias   (unchanged)
// ============================================================
__global__ void __launch_bounds__(256, 2)
lstm_gemm(const float* __restrict__ Aex, int asel,
          const float* __restrict__ Wl,
          const float* __restrict__ bl)
{
    const float* A = (asel == 0) ? Aex : (asel == 1 ? g_xbuf0 : g_xbuf1);
    float* Cout = g_gates;

    __shared__ __align__(16) float As[16][128];
    __shared__ __align__(16) float Bs[16][128];

    const int tid = threadIdx.x;
    const int n0 = blockIdx.x * 128;
    const int m0 = blockIdx.y * 128;
    const int tx = tid & 15, ty = tid >> 4;

    const int lr = tid >> 2;
    const int lk4 = tid & 3;

    unsigned long long acc[8][4];
#pragma unroll
    for (int i = 0; i < 8; i++)
#pragma unroll
        for (int j = 0; j < 4; j++) acc[i][j] = 0ull;

    const float* aP0 = A  + (size_t)(m0 + lr)      * 256 + lk4 * 4;
    const float* aP1 = A  + (size_t)(m0 + lr + 64) * 256 + lk4 * 4;
    const float* bP0 = Wl + (size_t)(n0 + lr)      * 256 + lk4 * 4;
    const float* bP1 = Wl + (size_t)(n0 + lr + 64) * 256 + lk4 * 4;

    float4 a0 = *(const float4*)(aP0);
    float4 a1 = *(const float4*)(aP1);
    float4 w0 = *(const float4*)(bP0);
    float4 w1 = *(const float4*)(bP1);

    for (int kt = 0; kt < 256; kt += 16) {
        __syncthreads();
        {
            int kb = lk4 * 4;
            As[kb + 0][lr] = a0.x; As[kb + 1][lr] = a0.y;
            As[kb + 2][lr] = a0.z; As[kb + 3][lr] = a0.w;
            As[kb + 0][lr + 64] = a1.x; As[kb + 1][lr + 64] = a1.y;
            As[kb + 2][lr + 64] = a1.z; As[kb + 3][lr + 64] = a1.w;
            Bs[kb + 0][lr] = w0.x; Bs[kb + 1][lr] = w0.y;
            Bs[kb + 2][lr] = w0.z; Bs[kb + 3][lr] = w0.w;
            Bs[kb + 0][lr + 64] = w1.x; Bs[kb + 1][lr + 64] = w1.y;
            Bs[kb + 2][lr + 64] = w1.z; Bs[kb + 3][lr + 64] = w1.w;
        }
        __syncthreads();

        if (kt < 240) {
            a0 = *(const float4*)(aP0 + kt + 16);
            a1 = *(const float4*)(aP1 + kt + 16);
            w0 = *(const float4*)(bP0 + kt + 16);
            w1 = *(const float4*)(bP1 + kt + 16);
        }

#pragma unroll
        for (int k = 0; k < 16; k++) {
            unsigned long long b2[4];
#pragma unroll
            for (int j = 0; j < 4; j++)
                b2[j] = *(const unsigned long long*)&Bs[k][tx * 8 + 2 * j];
            float4 af0 = *(const float4*)&As[k][ty * 8];
            float4 af1 = *(const float4*)&As[k][ty * 8 + 4];
            float a[8] = {af0.x, af0.y, af0.z, af0.w, af1.x, af1.y, af1.z, af1.w};
#pragma unroll
            for (int i = 0; i < 8; i++) {
                unsigned long long a2 = dup2(a[i]);
#pragma unroll
                for (int j = 0; j < 4; j++) ffma2(acc[i][j], a2, b2[j]);
            }
        }
    }

    float bias_r[8];
#pragma unroll
    for (int j = 0; j < 8; j++) bias_r[j] = bl[n0 + tx * 8 + j];
#pragma unroll
    for (int i = 0; i < 8; i++) {
        float o[8];
#pragma unroll
        for (int j = 0; j < 4; j++) {
            float2 v = unpack2(acc[i][j]);
            o[2 * j + 0] = v.x + bias_r[2 * j + 0];
            o[2 * j + 1] = v.y + bias_r[2 * j + 1];
        }
        float* crow = Cout + (size_t)(m0 + ty * 8 + i) * G4 + n0 + tx * 8;
        *(float4*)(crow + 0) = make_float4(o[0], o[1], o[2], o[3]);
        *(float4*)(crow + 4) = make_float4(o[4], o[5], o[6], o[7]);
    }
}

// ============================================================
// Recurrence scan with BATCH-PIPELINED half-steps.
// 16 clusters x 8 CTAs x 256 thr; cluster owns batches {2c,2c+1}.
// Each step = half-step(batch0) then half-step(batch1); batch b's
// st.async broadcast flight hides behind the OTHER batch's compute.
// 4 transaction mbarriers: {batch0,batch1} x {even,odd}, 1024 B
// each (8 ranks x 16 lanes x 8 B). expect_tx reposted right after
// each wait (ordered before any peer's next-phase bytes because
// those require this CTA's not-yet-issued send). Epilogue spread:
// lanes sub=0..3 compute one gate each (single-sigma path), gather
// at sub==0 via 3 shfls.
// ============================================================
__global__ void __launch_bounds__(256, 1) __cluster_dims__(8, 1, 1)
lstm_scan(const float* __restrict__ Rl,
          const float* __restrict__ h0,
          const float* __restrict__ c0,
          float* __restrict__ xex, int osel)
{
    float* xnext = (osel == 2) ? xex : (osel == 0 ? g_xbuf0 : g_xbuf1);
    const float* gates = g_gates;

    __shared__ __align__(16) float hs0[2][H];       // batch0: buf, hidden
    __shared__ __align__(16) float hs1[2][H];       // batch1
    __shared__ __align__(16) float hnew0[2][32];    // step parity, jj
    __shared__ __align__(16) float hnew1[2][32];
    __shared__ __align__(8) unsigned long long mbars[4];  // b0e,b0o,b1e,b1o

    const int tid = threadIdx.x;
    const int rank = (int)ctarank();
    const int bb0 = (blockIdx.x >> 3) * 2;   // first batch of this cluster
    const int lane = tid & 31;
    const int sub = tid & 7;
    const int jj = tid >> 3;
    const int hidx = rank * 32 + jj;
    const int w = tid >> 5;                   // warp = destination rank

    // ---- register-resident R slice: 4 gates x 16 column pairs ----
    unsigned long long Rf[4][16];
#pragma unroll
    for (int g = 0; g < 4; g++) {
        const float* base = Rl + (size_t)(g * 256 + hidx) * 256;
#pragma unroll
        for (int k2 = 0; k2 < 16; k2++)
            Rf[g][k2] = *(const unsigned long long*)(base + sub * 2 + 16 * k2);
    }

    // ---- initial h (buf 0) and c (gather lanes sub==0, both batches) ----
    for (int i = tid; i < H; i += 256) {
        hs0[0][i] = h0[(size_t)(bb0 + 0) * H + i];
        hs1[0][i] = h0[(size_t)(bb0 + 1) * H + i];
    }
    float creg0 = 0.f, creg1 = 0.f;
    if (sub == 0) {
        creg0 = c0[(size_t)(bb0 + 0) * H + hidx];
        creg1 = c0[(size_t)(bb0 + 1) * H + hidx];
    }

    // gate-x: lanes sub<4 hold gate 'sub' for both batches, one step ahead
    const float* gb0 = gates + (size_t)(bb0 + 0) * G4 + sub * 256 + hidx;
    const float* gb1 = gates + (size_t)(bb0 + 1) * G4 + sub * 256 + hidx;
    float gcur0 = 0.f, gcur1 = 0.f;
    if (sub < 4) { gcur0 = gb0[0]; gcur1 = gb1[0]; }   // t = 0

    // ---- loop-invariant DSMEM addresses (warp w -> rank w, lanes 0..15) ----
    uint32_t lmb[4];
#pragma unroll
    for (int i = 0; i < 4; i++) lmb[i] = smem_u32((const void*)&mbars[i]);
    const uint32_t d0b0 = mapa_rank(smem_u32(&hs0[0][rank * 32 + (lane & 15) * 2]), w);
    const uint32_t d0b1 = mapa_rank(smem_u32(&hs0[1][rank * 32 + (lane & 15) * 2]), w);
    const uint32_t d1b0 = mapa_rank(smem_u32(&hs1[0][rank * 32 + (lane & 15) * 2]), w);
    const uint32_t d1b1 = mapa_rank(smem_u32(&hs1[1][rank * 32 + (lane & 15) * 2]), w);
    uint32_t rmb[4];
#pragma unroll
    for (int i = 0; i < 4; i++) rmb[i] = mapa_rank(lmb[i], w);

    if (tid == 0) {
#pragma unroll
        for (int i = 0; i < 4; i++) {
            mbar_init(lmb[i], 1);
            mbar_expect(lmb[i], 1024);    // arm phase 0 of all 4 instances
        }
    }
    __syncthreads();
    asm volatile("barrier.cluster.arrive.aligned;" ::: "memory");
    asm volatile("barrier.cluster.wait.aligned;" ::: "memory");

    int p = 0;
    for (int t = 0; t < S; t++) {
        // prefetch next step's gate inputs (lanes sub<4, registers, MLP=2)
        float gn0 = 0.f, gn1 = 0.f;
        if (sub < 4) {
            const size_t off = (size_t)((t + 1 < S) ? (t + 1) : t) * (B * G4);
            gn0 = gb0[off];
            gn1 = gb1[off];
        }

        const int wi = (t - 1) & 1;                 // barrier idx for waits
        const uint32_t par = (uint32_t)(((t - 1) >> 1) & 1);

        // ================= batch 0 half-step =================
        if (t > 0) {
            mbar_wait(lmb[wi], par);                // h0(t) arrived
            if (tid == 0) mbar_expect(lmb[wi], 1024);
        }
        {
            unsigned long long acc[4] = {0ull, 0ull, 0ull, 0ull};
            const float* hp = &hs0[p][sub * 2];
#pragma unroll
            for (int k2 = 0; k2 < 16; k2++) {
                unsigned long long hv = *(const unsigned long long*)(hp + 16 * k2);
#pragma unroll
                for (int g = 0; g < 4; g++) ffma2(acc[g], Rf[g][k2], hv);
            }
            float red[4];
#pragma unroll
            for (int g = 0; g < 4; g++) {
                float2 v = unpack2(acc[g]);
                float s = v.x + v.y;
                s += __shfl_xor_sync(0xffffffffu, s, 1);
                s += __shfl_xor_sync(0xffffffffu, s, 2);
                s += __shfl_xor_sync(0xffffffffu, s, 4);
                red[g] = s;
            }
            // spread epilogue: lane computes gate (sub&3); tanh = 2*sigm(2x)-1
            const int sg3 = sub & 3;
            float xin = red[sg3] + gcur0;
            float xs = (sg3 == 2) ? 2.0f * xin : xin;
            float sv = fsigm(xs);
            float av = (sg3 == 2) ? 2.0f * sv - 1.0f : sv;
            float fv = __shfl_sync(0xffffffffu, av, lane + 1);
            float gv = __shfl_sync(0xffffffffu, av, lane + 2);
            float ov = __shfl_sync(0xffffffffu, av, lane + 3);
            if (sub == 0) {
                float cnew = fv * creg0 + av * gv;
                creg0 = cnew;
                hnew0[t & 1][jj] = ov * ftanh(cnew);
            }
        }
        __syncthreads();
        if ((lane & 31) < 16) {
            unsigned long long v =
                *(const unsigned long long*)&hnew0[t & 1][(lane & 15) * 2];
            st_async_b64((p == 0) ? d0b1 : d0b0, v, rmb[t & 1]);
        }
        if (tid < 8) {
            float4 v = ((const float4*)&hnew0[t & 1][0])[tid];
            *(float4*)&xnext[(size_t)(t * B + bb0) * H + rank * 32 + tid * 4] = v;
        }

        // ================= batch 1 half-step =================
        // (batch0's broadcast flight hides behind this entire block)
        if (t > 0) {
            mbar_wait(lmb[2 + wi], par);            // h1(t) arrived
            if (tid == 0) mbar_expect(lmb[2 + wi], 1024);
        }
        {
            unsigned long long acc[4] = {0ull, 0ull, 0ull, 0ull};
            const float* hp = &hs1[p][sub * 2];
#pragma unroll
            for (int k2 = 0; k2 < 16; k2++) {
                unsigned long long hv = *(const unsigned long long*)(hp + 16 * k2);
#pragma unroll
                for (int g = 0; g < 4; g++) ffma2(acc[g], Rf[g][k2], hv);
            }
            float red[4];
#pragma unroll
            for (int g = 0; g < 4; g++) {
                float2 v = unpack2(acc[g]);
                float s = v.x + v.y;
                s += __shfl_xor_sync(0xffffffffu, s, 1);
                s += __shfl_xor_sync(0xffffffffu, s, 2);
                s += __shfl_xor_sync(0xffffffffu, s, 4);
                red[g] = s;
            }
            const int sg3 = sub & 3;
            float xin = red[sg3] + gcur1;
            float xs = (sg3 == 2) ? 2.0f * xin : xin;
            float sv = fsigm(xs);
            float av = (sg3 == 2) ? 2.0f * sv - 1.0f : sv;
            float fv = __shfl_sync(0xffffffffu, av, lane + 1);
            float gv = __shfl_sync(0xffffffffu, av, lane + 2);
            float ov = __shfl_sync(0xffffffffu, av, lane + 3);
            if (sub == 0) {
                float cnew = fv * creg1 + av * gv;
                creg1 = cnew;
                hnew1[t & 1][jj] = ov * ftanh(cnew);
            }
        }
        __syncthreads();
        if ((lane & 31) < 16) {
            unsigned long long v =
                *(const unsigned long long*)&hnew1[t & 1][(lane & 15) * 2];
            st_async_b64((p == 0) ? d1b1 : d1b0, v, rmb[2 + (t & 1)]);
        }
        if (tid < 8) {
            float4 v = ((const float4*)&hnew1[t & 1][0])[tid];
            *(float4*)&xnext[(size_t)(t * B + bb0 + 1) * H + rank * 32 + tid * 4] = v;
        }

        gcur0 = gn0;
        gcur1 = gn1;
        p ^= 1;
    }

    // keep smem alive until every peer's last st.async has landed
    asm volatile("barrier.cluster.arrive.aligned;" ::: "memory");
    asm volatile("barrier.cluster.wait.aligned;" ::: "memory");
}

// ============================================================
// Host: 4 x (GEMM, SCAN), ping-pong x buffers, all on stream 0.
// ============================================================
extern "C" void kernel_launch(void* const* d_in, const int* in_sizes, int n_in,
                              void* d_out, int out_size)
{
    const float* h_data = (const float*)d_in[0];
    const float* x_data = (const float*)d_in[1];
    const float* c_data = (const float*)d_in[2];
    const float* W      = (const float*)d_in[3];
    const float* R      = (const float*)d_in[4];
    const float* bias   = (const float*)d_in[5];
    float* out = (float*)d_out;

    const dim3 ggrid(8, 256);               // N/128, M/128
    const size_t wstride = (size_t)G4 * H;

    lstm_gemm<<<ggrid, 256>>>(x_data, 0, W + 0 * wstride, bias + 0 * G4);
    lstm_scan<<<128, 256>>>(R + 0 * wstride,
                            h_data + 0 * (size_t)LSTRIDE,
                            c_data + 0 * (size_t)LSTRIDE,
                            nullptr, 0);
    lstm_gemm<<<ggrid, 256>>>(nullptr, 1, W + 1 * wstride, bias + 1 * G4);
    lstm_scan<<<128, 256>>>(R + 1 * wstride,
                            h_data + 1 * (size_t)LSTRIDE,
                            c_data + 1 * (size_t)LSTRIDE,
                            nullptr, 1);
    lstm_gemm<<<ggrid, 256>>>(nullptr, 2, W + 2 * wstride, bias + 2 * G4);
    lstm_scan<<<128, 256>>>(R + 2 * wstride,
                            h_data + 2 * (size_t)LSTRIDE,
                            c_data + 2 * (size_t)LSTRIDE,
                            nullptr, 0);
    lstm_gemm<<<ggrid, 256>>>(nullptr, 1, W + 3 * wstride, bias + 3 * G4);
    lstm_scan<<<128, 256>>>(R + 3 * wstride,
                            h_data + 3 * (size_t)LSTRIDE,
                            c_data + 3 * (size_t)LSTRIDE,
                            out, 2);
}

// round 17
// speedup vs baseline: 1.1519x; 1.1519x over previous
#include <cuda_runtime.h>
#include <cstdint>

#define H 256
#define B 32
#define S 1024
#define NL 4
#define NE (H * B)              // 8192
#define G4 (4 * H)              // 1024
#define MROWS (S * B)           // 32768
#define LSTRIDE ((S + 1) * NE)  // per-layer h0/c0 slab stride

// -------- static scratch (allowed: __device__ globals) --------
__device__ float g_gates[(size_t)MROWS * G4];   // 128 MB: [t*B+b][4H]
__device__ float g_xbuf0[(size_t)MROWS * H];    // 32 MB:  [t*B+b][H]
__device__ float g_xbuf1[(size_t)MROWS * H];    // 32 MB

// -------- helpers --------
__device__ __forceinline__ void ffma2(unsigned long long& d,
                                      unsigned long long a,
                                      unsigned long long b) {
    asm("fma.rn.f32x2 %0, %1, %2, %0;" : "+l"(d) : "l"(a), "l"(b));
}
__device__ __forceinline__ unsigned long long dup2(float a) {
    unsigned long long r;
    asm("mov.b64 %0, {%1, %1};" : "=l"(r) : "f"(a));
    return r;
}
__device__ __forceinline__ float2 unpack2(unsigned long long v) {
    float2 f;
    asm("mov.b64 {%0, %1}, %2;" : "=f"(f.x), "=f"(f.y) : "l"(v));
    return f;
}
__device__ __forceinline__ uint32_t smem_u32(const void* p) {
    return (uint32_t)__cvta_generic_to_shared(p);
}
__device__ __forceinline__ uint32_t ctarank() {
    uint32_t r;
    asm("mov.u32 %0, %%cluster_ctarank;" : "=r"(r));
    return r;
}
__device__ __forceinline__ uint32_t mapa_rank(uint32_t laddr, int r) {
    uint32_t ra;
    asm("mapa.shared::cluster.u32 %0, %1, %2;" : "=r"(ra) : "r"(laddr), "r"(r));
    return ra;
}
// fast, branch-free activations (rel err ~1e-6; saturate correctly)
__device__ __forceinline__ float fsigm(float x) {
    return __fdividef(1.0f, 1.0f + __expf(-x));
}
__device__ __forceinline__ float ftanh(float x) {
    return __fdividef(2.0f, 1.0f + __expf(-2.0f * x)) - 1.0f;
}
__device__ __forceinline__ void mbar_init(uint32_t a, int cnt) {
    asm volatile("mbarrier.init.shared.b64 [%0], %1;" :: "r"(a), "r"(cnt) : "memory");
}
__device__ __forceinline__ void mbar_expect(uint32_t a, uint32_t bytes) {
    asm volatile("mbarrier.arrive.expect_tx.shared.b64 _, [%0], %1;"
                 :: "r"(a), "r"(bytes) : "memory");
}
// 16-B vector st.async: one tx-update of 16 B at the destination barrier
// (halves the per-step barrier update count vs .b64).
__device__ __forceinline__ void st_async_v4(uint32_t dst,
                                            uint32_t x0, uint32_t x1,
                                            uint32_t x2, uint32_t x3,
                                            uint32_t rbar) {
    asm volatile(
        "st.async.weak.shared::cluster.mbarrier::complete_tx::bytes.v4.b32 "
        "[%0], {%1, %2, %3, %4}, [%5];"
        :: "r"(dst), "r"(x0), "r"(x1), "r"(x2), "r"(x3), "r"(rbar) : "memory");
}
__device__ __forceinline__ void mbar_wait(uint32_t a, uint32_t parity) {
    uint32_t done;
    asm volatile(
        "{\n\t.reg .pred p;\n\t"
        "mbarrier.try_wait.parity.acquire.cta.shared::cta.b64 p, [%1], %2;\n\t"
        "selp.b32 %0, 1, 0, p;\n\t}"
        : "=r"(done) : "r"(a), "r"(parity) : "memory");
    if (!done) {
        asm volatile(
            "{\n\t.reg .pred P1;\n\t"
            "W_%=:\n\t"
            "mbarrier.try_wait.parity.acquire.cta.shared::cta.b64 P1, [%0], %1, 0x989680;\n\t"
            "@P1 bra.uni D_%=;\n\t"
            "bra.uni W_%=;\n\t"
            "D_%=:\n\t}"
            :: "r"(a), "r"(parity) : "memory");
    }
}

// ============================================================
// GEMM: C[M=32768, N=1024] = A[M,256] @ W^T + bias   (unchanged)
// ============================================================
__global__ void __launch_bounds__(256, 2)
lstm_gemm(const float* __restrict__ Aex, int asel,
          const float* __restrict__ Wl,
          const float* __restrict__ bl)
{
    const float* A = (asel == 0) ? Aex : (asel == 1 ? g_xbuf0 : g_xbuf1);
    float* Cout = g_gates;

    __shared__ __align__(16) float As[16][128];
    __shared__ __align__(16) float Bs[16][128];

    const int tid = threadIdx.x;
    const int n0 = blockIdx.x * 128;
    const int m0 = blockIdx.y * 128;
    const int tx = tid & 15, ty = tid >> 4;

    const int lr = tid >> 2;
    const int lk4 = tid & 3;

    unsigned long long acc[8][4];
#pragma unroll
    for (int i = 0; i < 8; i++)
#pragma unroll
        for (int j = 0; j < 4; j++) acc[i][j] = 0ull;

    const float* aP0 = A  + (size_t)(m0 + lr)      * 256 + lk4 * 4;
    const float* aP1 = A  + (size_t)(m0 + lr + 64) * 256 + lk4 * 4;
    const float* bP0 = Wl + (size_t)(n0 + lr)      * 256 + lk4 * 4;
    const float* bP1 = Wl + (size_t)(n0 + lr + 64) * 256 + lk4 * 4;

    float4 a0 = *(const float4*)(aP0);
    float4 a1 = *(const float4*)(aP1);
    float4 w0 = *(const float4*)(bP0);
    float4 w1 = *(const float4*)(bP1);

    for (int kt = 0; kt < 256; kt += 16) {
        __syncthreads();
        {
            int kb = lk4 * 4;
            As[kb + 0][lr] = a0.x; As[kb + 1][lr] = a0.y;
            As[kb + 2][lr] = a0.z; As[kb + 3][lr] = a0.w;
            As[kb + 0][lr + 64] = a1.x; As[kb + 1][lr + 64] = a1.y;
            As[kb + 2][lr + 64] = a1.z; As[kb + 3][lr + 64] = a1.w;
            Bs[kb + 0][lr] = w0.x; Bs[kb + 1][lr] = w0.y;
            Bs[kb + 2][lr] = w0.z; Bs[kb + 3][lr] = w0.w;
            Bs[kb + 0][lr + 64] = w1.x; Bs[kb + 1][lr + 64] = w1.y;
            Bs[kb + 2][lr + 64] = w1.z; Bs[kb + 3][lr + 64] = w1.w;
        }
        __syncthreads();

        if (kt < 240) {
            a0 = *(const float4*)(aP0 + kt + 16);
            a1 = *(const float4*)(aP1 + kt + 16);
            w0 = *(const float4*)(bP0 + kt + 16);
            w1 = *(const float4*)(bP1 + kt + 16);
        }

#pragma unroll
        for (int k = 0; k < 16; k++) {
            unsigned long long b2[4];
#pragma unroll
            for (int j = 0; j < 4; j++)
                b2[j] = *(const unsigned long long*)&Bs[k][tx * 8 + 2 * j];
            float4 af0 = *(const float4*)&As[k][ty * 8];
            float4 af1 = *(const float4*)&As[k][ty * 8 + 4];
            float a[8] = {af0.x, af0.y, af0.z, af0.w, af1.x, af1.y, af1.z, af1.w};
#pragma unroll
            for (int i = 0; i < 8; i++) {
                unsigned long long a2 = dup2(a[i]);
#pragma unroll
                for (int j = 0; j < 4; j++) ffma2(acc[i][j], a2, b2[j]);
            }
        }
    }

    float bias_r[8];
#pragma unroll
    for (int j = 0; j < 8; j++) bias_r[j] = bl[n0 + tx * 8 + j];
#pragma unroll
    for (int i = 0; i < 8; i++) {
        float o[8];
#pragma unroll
        for (int j = 0; j < 4; j++) {
            float2 v = unpack2(acc[i][j]);
            o[2 * j + 0] = v.x + bias_r[2 * j + 0];
            o[2 * j + 1] = v.y + bias_r[2 * j + 1];
        }
        float* crow = Cout + (size_t)(m0 + ty * 8 + i) * G4 + n0 + tx * 8;
        *(float4*)(crow + 0) = make_float4(o[0], o[1], o[2], o[3]);
        *(float4*)(crow + 4) = make_float4(o[4], o[5], o[6], o[7]);
    }
}

// ============================================================
// Recurrence scan (R15 structure, syncthreads-free loop).
// 16 clusters x 8 CTAs x 256 thr; cluster owns batches {2c,2c+1};
// CTA rank owns 32 h-indices x 4 gates (R in registers).
// Per step: wait -> dot (FFMA2) -> 8-lane shfl reduce -> owner
// epilogue (sub<2, h in REGISTERS) -> warp self-packs 4 h values
// per batch via 3 shfls -> lanes 0/1 of each warp issue EIGHT
// 16-B st.async.v4.b32 (one per rank) + one STG.128 of the same
// packet to xnext. No __syncthreads in the loop: warps are fully
// decoupled; causality (peer's t+1 bytes require THIS warp's t
// send, which follows this warp's hs[p] reads) protects buffers.
// 128 x 16-B tx-updates per barrier per step (was 256 x 8-B).
// ============================================================
__global__ void __launch_bounds__(256, 1) __cluster_dims__(8, 1, 1)
lstm_scan(const float* __restrict__ Rl,
          const float* __restrict__ h0,
          const float* __restrict__ c0,
          float* __restrict__ xex, int osel)
{
    float* xnext = (osel == 2) ? xex : (osel == 0 ? g_xbuf0 : g_xbuf1);
    const float* gates = g_gates;

    __shared__ __align__(16) float hs[2][2][H];          // buffer, batch, hidden
    __shared__ __align__(8) unsigned long long mbars[2]; // even/odd step

    const int tid = threadIdx.x;
    const int rank = (int)ctarank();
    const int b0 = (blockIdx.x >> 3) * 2;
    const int lane = tid & 31;
    const int sub = tid & 7;
    const int jj = tid >> 3;
    const int w = tid >> 5;              // warp id; warp covers jj = 4w..4w+3
    const int hidx = rank * 32 + jj;

    // ---- register-resident R slice: 4 gates x 16 column pairs ----
    unsigned long long Rf[4][16];
#pragma unroll
    for (int g = 0; g < 4; g++) {
        const float* base = Rl + (size_t)(g * 256 + hidx) * 256;
#pragma unroll
        for (int k2 = 0; k2 < 16; k2++)
            Rf[g][k2] = *(const unsigned long long*)(base + sub * 2 + 16 * k2);
    }

    // ---- initial h and c ----
    for (int i = tid; i < 2 * H; i += 256) {
        int b = i >> 8, idx = i & 255;
        hs[0][b][idx] = h0[(size_t)(b0 + b) * H + idx];
    }
    const int myb = sub;                 // owner lanes: sub==b (b in {0,1})
    const bool is_owner = (sub < 2);
    float creg = 0.f;
    if (is_owner) creg = c0[(size_t)(b0 + myb) * H + hidx];

    // owner-register gates: gcur = step t's 4 gate inputs (prefetch t+1)
    const float* gbase = gates + (size_t)(b0 + myb) * G4 + hidx;
    float gcur[4] = {0.f, 0.f, 0.f, 0.f};
    if (is_owner) {
#pragma unroll
        for (int g = 0; g < 4; g++) gcur[g] = gbase[g * 256];     // t = 0
    }

    // ---- loop-invariant addresses ----
    // send target: batch (lane&1) slice [rank*32 + 4w .. +3] in hs[buf]
    const int sb = lane & 1;
    const uint32_t lA = smem_u32(&hs[1][sb][rank * 32 + w * 4]);  // buf 1
    const uint32_t lB = smem_u32(&hs[0][sb][rank * 32 + w * 4]);  // buf 0
    uint32_t dA[8], dB[8], rA[8], rB[8];
    const uint32_t lmb0 = smem_u32((const void*)&mbars[0]);
    const uint32_t lmb1 = smem_u32((const void*)&mbars[1]);
#pragma unroll
    for (int r = 0; r < 8; r++) {
        dA[r] = mapa_rank(lA, r);
        dB[r] = mapa_rank(lB, r);
        rA[r] = mapa_rank(lmb0, r);
        rB[r] = mapa_rank(lmb1, r);
    }

    if (tid == 0) {
        mbar_init(lmb0, 1);
        mbar_init(lmb1, 1);
        mbar_expect(lmb0, 2048);   // arm t = 0
    }
    __syncthreads();
    asm volatile("barrier.cluster.arrive.aligned;" ::: "memory");
    asm volatile("barrier.cluster.wait.aligned;" ::: "memory");

    int p = 0;
    for (int t = 0; t < S; t++) {
        // owner-only register prefetch of step t+1 gate inputs (MLP=4)
        float gnxt[4];
        if (is_owner) {
            const float* gp = gbase + (size_t)((t + 1 < S) ? (t + 1) : t) * (B * G4);
#pragma unroll
            for (int g = 0; g < 4; g++) gnxt[g] = gp[g * 256];
        }

        // ---- dot: acc[g][b] over this thread's 32 columns ----
        unsigned long long acc[4][2] = {{0ull, 0ull}, {0ull, 0ull},
                                        {0ull, 0ull}, {0ull, 0ull}};
        const float* hp0 = &hs[p][0][sub * 2];
        const float* hp1 = &hs[p][1][sub * 2];
#pragma unroll
        for (int k2 = 0; k2 < 16; k2++) {
            unsigned long long h0v = *(const unsigned long long*)(hp0 + 16 * k2);
            unsigned long long h1v = *(const unsigned long long*)(hp1 + 16 * k2);
#pragma unroll
            for (int g = 0; g < 4; g++) {
                ffma2(acc[g][0], Rf[g][k2], h0v);
                ffma2(acc[g][1], Rf[g][k2], h1v);
            }
        }

        // ---- reduce over the 8-lane column group ----
        float red[4][2];
#pragma unroll
        for (int g = 0; g < 4; g++)
#pragma unroll
            for (int b = 0; b < 2; b++) {
                float2 v = unpack2(acc[g][b]);
                float s = v.x + v.y;
                s += __shfl_xor_sync(0xffffffffu, s, 1);
                s += __shfl_xor_sync(0xffffffffu, s, 2);
                s += __shfl_xor_sync(0xffffffffu, s, 4);
                red[g][b] = s;
            }

        // ---- cell epilogue (owner lanes sub<2; h stays in a register) ----
        float hval = 0.f;
        if (is_owner) {
            float gi = red[0][myb] + gcur[0];
            float gf = red[1][myb] + gcur[1];
            float gG = red[2][myb] + gcur[2];
            float go = red[3][myb] + gcur[3];
            float iv = fsigm(gi);
            float fv = fsigm(gf);
            float gv = ftanh(gG);
            float ov = fsigm(go);
            float cnew = fv * creg + iv * gv;
            creg = cnew;
            hval = ov * ftanh(cnew);
        }
#pragma unroll
        for (int g = 0; g < 4; g++) gcur[g] = gnxt[g];

        // ---- warp self-pack: h[4w..4w+3] of batch (lane&1) into 4 regs ----
        float x0 = __shfl_sync(0xffffffffu, hval, sb + 0);
        float x1 = __shfl_sync(0xffffffffu, hval, sb + 8);
        float x2 = __shfl_sync(0xffffffffu, hval, sb + 16);
        float x3 = __shfl_sync(0xffffffffu, hval, sb + 24);

        // ---- lanes 0/1: 8 x 16-B st.async (one per rank) + xnext STG ----
        if (lane < 2) {
            uint32_t u0 = __float_as_uint(x0), u1 = __float_as_uint(x1);
            uint32_t u2 = __float_as_uint(x2), u3 = __float_as_uint(x3);
#pragma unroll
            for (int r = 0; r < 8; r++) {
                st_async_v4((p == 0) ? dA[r] : dB[r], u0, u1, u2, u3,
                            (t & 1) ? rB[r] : rA[r]);
            }
            *(float4*)&xnext[(size_t)(t * B + b0 + sb) * H + rank * 32 + w * 4] =
                make_float4(x0, x1, x2, x3);
        }
        // post expect for step t+1 (ordered before any peer's t+1 bytes:
        // those require this CTA's step-t sends above)
        if (tid == 0) mbar_expect((t & 1) ? lmb0 : lmb1, 2048);

        // wait for all 2048 B of step t to land in hs[p^1]
        mbar_wait((t & 1) ? lmb1 : lmb0, (uint32_t)((t >> 1) & 1));
        p ^= 1;
    }

    // keep smem alive until every peer's last st.async has landed
    asm volatile("barrier.cluster.arrive.aligned;" ::: "memory");
    asm volatile("barrier.cluster.wait.aligned;" ::: "memory");
}

// ============================================================
// Host: 4 x (GEMM, SCAN), ping-pong x buffers, all on stream 0.
// ============================================================
extern "C" void kernel_launch(void* const* d_in, const int* in_sizes, int n_in,
                              void* d_out, int out_size)
{
    const float* h_data = (const float*)d_in[0];
    const float* x_data = (const float*)d_in[1];
    const float* c_data = (const float*)d_in[2];
    const float* W      = (const float*)d_in[3];
    const float* R      = (const float*)d_in[4];
    const float* bias   = (const float*)d_in[5];
    float* out = (float*)d_out;

    const dim3 ggrid(8, 256);               // N/128, M/128
    const size_t wstride = (size_t)G4 * H;

    lstm_gemm<<<ggrid, 256>>>(x_data, 0, W + 0 * wstride, bias + 0 * G4);
    lstm_scan<<<128, 256>>>(R + 0 * wstride,
                            h_data + 0 * (size_t)LSTRIDE,
                            c_data + 0 * (size_t)LSTRIDE,
                            nullptr, 0);
    lstm_gemm<<<ggrid, 256>>>(nullptr, 1, W + 1 * wstride, bias + 1 * G4);
    lstm_scan<<<128, 256>>>(R + 1 * wstride,
                            h_data + 1 * (size_t)LSTRIDE,
                            c_data + 1 * (size_t)LSTRIDE,
                            nullptr, 1);
    lstm_gemm<<<ggrid, 256>>>(nullptr, 2, W + 2 * wstride, bias + 2 * G4);
    lstm_scan<<<128, 256>>>(R + 2 * wstride,
                            h_data + 2 * (size_t)LSTRIDE,
                            c_data + 2 * (size_t)LSTRIDE,
                            nullptr, 0);
    lstm_gemm<<<ggrid, 256>>>(nullptr, 1, W + 3 * wstride, bias + 3 * G4);
    lstm_scan<<<128, 256>>>(R + 3 * wstride,
                            h_data + 3 * (size_t)LSTRIDE,
                            c_data + 3 * (size_t)LSTRIDE,
                            out, 2);
}